// round 5
// baseline (speedup 1.0000x reference)
#include <cuda_runtime.h>
#include <cstdint>

#define Sdim 512
#define SS (Sdim * Sdim)
#define Bn 8
#define KT 32
#define NTHREADS 128

// Sheared copy of x: Dall[i][b][j] = x[b][j][i-j] for j <= i.
__device__ float Dall[Sdim][Bn][Sdim];   // 8.4 MB static scratch

// ---- packed f32x2 helpers (FFMA2 only reachable via PTX) ----
__device__ __forceinline__ uint64_t pk2(float lo, float hi) {
    uint64_t r;
    asm("mov.b64 %0, {%1, %2};" : "=l"(r) : "f"(lo), "f"(hi));
    return r;
}
__device__ __forceinline__ float2 upk2(uint64_t v) {
    float2 r;
    asm("mov.b64 {%0, %1}, %2;" : "=f"(r.x), "=f"(r.y) : "l"(v));
    return r;
}
__device__ __forceinline__ void ffma2(uint64_t& acc, uint64_t a, uint64_t b) {
    asm("fma.rn.f32x2 %0, %1, %2, %0;" : "+l"(acc) : "l"(a), "l"(b));
}

// Pass-through copy: warp per row, float4 body.
// out[b][r][c] = x[b][r][c] for c >= S - r.
__global__ void __launch_bounds__(256)
copy_tail_kernel(const float* __restrict__ x, float* __restrict__ out) {
    const int row = blockIdx.x * 8 + (threadIdx.x >> 5);   // 0..4095 = b*512+r
    const int lane = threadIdx.x & 31;
    const int r = row & (Sdim - 1);
    const int c0 = Sdim - r;                                // segment start
    if (c0 >= Sdim) return;                                 // r == 0
    const float* src = x + (size_t)row * Sdim;
    float* dst = out + (size_t)row * Sdim;

    int head = (4 - (c0 & 3)) & 3;
    if (head > Sdim - c0) head = Sdim - c0;
    if (lane < head) dst[c0 + lane] = src[c0 + lane];
    const int c1 = c0 + head;
    const int n4 = (Sdim - c1) >> 2;                        // Sdim%4==0 -> no tail
    const float4* s4 = (const float4*)(src + c1);
    float4* d4 = (float4*)(dst + c1);
    for (int t = lane; t < n4; t += 32) d4[t] = s4[t];
}

// Shear transpose: Dall[i][b][j] = x[b][j][i-j]. 32x32 smem tiles; both
// global streams coalesced.
__global__ void __launch_bounds__(1024)
shear_kernel(const float* __restrict__ x) {
    const int b  = blockIdx.z;
    const int i0 = blockIdx.y * 32;
    const int j0 = blockIdx.x * 32;
    if (i0 + 31 < j0) return;

    __shared__ float tile[32][33];
    const int tx = threadIdx.x;
    const int ty = threadIdx.y;

    const int c = i0 - j0 + tx - ty;
    float v = 0.0f;
    if (c >= 0 && c < Sdim)
        v = x[((size_t)b * Sdim + (j0 + ty)) * Sdim + c];
    tile[ty][tx] = v;
    __syncthreads();

    const int i = i0 + ty;
    const int j = j0 + tx;
    if (j <= i)
        Dall[i][b][j] = tile[tx][ty];
}

// One CTA per (diagonal i, 32-wide k tile), 128 threads (4 warps).
//   out[b, i-k, k] = sum_j W[i,k,j] * D[b][j] + bias[i,k]
__global__ void __launch_bounds__(NTHREADS)
diag_linear_kernel(const float* __restrict__ W,
                   const float* __restrict__ bias,
                   float* __restrict__ out) {
    const int i = Sdim - 1 - (int)blockIdx.y;   // heavy diagonals first
    const int k0 = (int)blockIdx.x * KT;
    if (k0 > i) return;

    const int len = i + 1;
    const int kend = min(k0 + KT, len);

    __shared__ float Ds[Bn][Sdim];

    const int tid = threadIdx.x;

    // Coalesced copy of the pre-sheared diagonal (L2-resident Dall).
    {
        const int n4 = (len + 3) >> 2;
        const float4* src = (const float4*)&Dall[i][0][0];
        float4* dst = (float4*)&Ds[0][0];
        #pragma unroll
        for (int b = 0; b < Bn; b++) {
            for (int t = tid; t < n4; t += NTHREADS)
                dst[b * (Sdim / 4) + t] = src[b * (Sdim / 4) + t];
        }
    }
    __syncthreads();

    const int warp = tid >> 5;
    const int lane = tid & 31;
    const float* Wbase = W + (size_t)i * Sdim * Sdim;

    if (k0 + KT <= len) {
        // Full tile: each warp handles 4 k-rows per pass, 2 passes.
        // Packed-pair accumulation: acc2 holds (even-j, odd-j) partials.
        #pragma unroll
        for (int p = 0; p < 2; p++) {
            const int kk = k0 + p * 16 + warp * 4;
            const float4* wr0 = (const float4*)(Wbase + (size_t)(kk + 0) * Sdim);
            const float4* wr1 = (const float4*)(Wbase + (size_t)(kk + 1) * Sdim);
            const float4* wr2 = (const float4*)(Wbase + (size_t)(kk + 2) * Sdim);
            const float4* wr3 = (const float4*)(Wbase + (size_t)(kk + 3) * Sdim);

            uint64_t acc2[4][Bn];
            const uint64_t z = pk2(0.0f, 0.0f);
            #pragma unroll
            for (int u = 0; u < 4; u++)
                #pragma unroll
                for (int b = 0; b < Bn; b++) acc2[u][b] = z;

            const int len4 = len >> 2;
            for (int t = lane; t < len4; t += 32) {
                float4 w0 = __ldcs(wr0 + t);
                float4 w1 = __ldcs(wr1 + t);
                float4 w2 = __ldcs(wr2 + t);
                float4 w3 = __ldcs(wr3 + t);
                uint64_t w0l = pk2(w0.x, w0.y), w0h = pk2(w0.z, w0.w);
                uint64_t w1l = pk2(w1.x, w1.y), w1h = pk2(w1.z, w1.w);
                uint64_t w2l = pk2(w2.x, w2.y), w2h = pk2(w2.z, w2.w);
                uint64_t w3l = pk2(w3.x, w3.y), w3h = pk2(w3.z, w3.w);
                #pragma unroll
                for (int b = 0; b < Bn; b++) {
                    float4 d = ((const float4*)Ds[b])[t];
                    uint64_t dl = pk2(d.x, d.y), dh = pk2(d.z, d.w);
                    ffma2(acc2[0][b], w0l, dl); ffma2(acc2[0][b], w0h, dh);
                    ffma2(acc2[1][b], w1l, dl); ffma2(acc2[1][b], w1h, dh);
                    ffma2(acc2[2][b], w2l, dl); ffma2(acc2[2][b], w2h, dh);
                    ffma2(acc2[3][b], w3l, dl); ffma2(acc2[3][b], w3h, dh);
                }
            }

            // Collapse packed pairs to scalars.
            float acc[4][Bn];
            #pragma unroll
            for (int u = 0; u < 4; u++)
                #pragma unroll
                for (int b = 0; b < Bn; b++) {
                    float2 v = upk2(acc2[u][b]);
                    acc[u][b] = v.x + v.y;
                }

            // Remainder (len % 4)
            const int rem = len & 3;
            if (lane < rem) {
                const int j = (len4 << 2) + lane;
                float w0s = Wbase[(size_t)(kk + 0) * Sdim + j];
                float w1s = Wbase[(size_t)(kk + 1) * Sdim + j];
                float w2s = Wbase[(size_t)(kk + 2) * Sdim + j];
                float w3s = Wbase[(size_t)(kk + 3) * Sdim + j];
                #pragma unroll
                for (int b = 0; b < Bn; b++) {
                    float dv = Ds[b][j];
                    acc[0][b] += w0s * dv;
                    acc[1][b] += w1s * dv;
                    acc[2][b] += w2s * dv;
                    acc[3][b] += w3s * dv;
                }
            }

            #pragma unroll
            for (int off = 16; off > 0; off >>= 1) {
                #pragma unroll
                for (int u = 0; u < 4; u++)
                    #pragma unroll
                    for (int b = 0; b < Bn; b++)
                        acc[u][b] += __shfl_xor_sync(0xffffffffu, acc[u][b], off);
            }

            if (lane == 0) {
                #pragma unroll
                for (int u = 0; u < 4; u++) {
                    const int k = kk + u;
                    const float bb = __ldg(bias + (size_t)i * Sdim + k);
                    const int r = i - k;
                    #pragma unroll
                    for (int b = 0; b < Bn; b++) {
                        out[(size_t)b * SS + (size_t)r * Sdim + k] = acc[u][b] + bb;
                    }
                }
            }
        }
    } else {
        // Boundary path (partial k tile): warp-per-k, stride 4.
        for (int k = k0 + warp; k < kend; k += (NTHREADS / 32)) {
            const float* wrow = Wbase + (size_t)k * Sdim;
            const float4* w4p = (const float4*)wrow;

            float acc[Bn];
            #pragma unroll
            for (int b = 0; b < Bn; b++) acc[b] = 0.0f;

            const int len4 = len >> 2;
            for (int t = lane; t < len4; t += 32) {
                float4 w4 = __ldcs(w4p + t);
                #pragma unroll
                for (int b = 0; b < Bn; b++) {
                    float4 d = ((const float4*)Ds[b])[t];
                    acc[b] += w4.x * d.x + w4.y * d.y + w4.z * d.z + w4.w * d.w;
                }
            }
            for (int j = (len4 << 2) + lane; j < len; j += 32) {
                float w = wrow[j];
                #pragma unroll
                for (int b = 0; b < Bn; b++) acc[b] += w * Ds[b][j];
            }

            #pragma unroll
            for (int off = 16; off > 0; off >>= 1) {
                #pragma unroll
                for (int b = 0; b < Bn; b++)
                    acc[b] += __shfl_xor_sync(0xffffffffu, acc[b], off);
            }

            if (lane == 0) {
                const float bb = __ldg(bias + (size_t)i * Sdim + k);
                const int r = i - k;
                #pragma unroll
                for (int b = 0; b < Bn; b++) {
                    out[(size_t)b * SS + (size_t)r * Sdim + k] = acc[b] + bb;
                }
            }
        }
    }
}

extern "C" void kernel_launch(void* const* d_in, const int* in_sizes, int n_in,
                              void* d_out, int out_size) {
    const float* x = (const float*)d_in[0];
    const float* W = (const float*)d_in[1];
    const float* b = (const float*)d_in[2];
    float* out = (float*)d_out;

    copy_tail_kernel<<<(Bn * Sdim) / 8, 256>>>(x, out);

    dim3 sgrid(Sdim / 32, Sdim / 32, Bn);
    shear_kernel<<<sgrid, dim3(32, 32)>>>(x);

    dim3 grid(Sdim / KT, Sdim);
    diag_linear_kernel<<<grid, NTHREADS>>>(W, b, out);
}